// round 3
// baseline (speedup 1.0000x reference)
#include <cuda_runtime.h>
#include <cuda_bf16.h>

// ===========================================================================
// StaticMHCAdapter: out[b,t] = sum_s (h_res[s,t] + h_post[t]*h_pre[s]) * x[b,s]
// where h_res = sinkhorn_log(H_res_logits), h_pre/h_post = softmax(...).
// x = residuals reshaped [B=4, S=4, T=2048, D=2048].
// Entire op = 4x4 linear mix over streams -> pure HBM streaming (512 MB).
// ===========================================================================

#define NS 4                      // NUM_STREAMS
#define SINKHORN_ITERS 10
#define SINKHORN_TAU 0.05f

__device__ float g_M[16];         // g_M[t*NS+s] = h_res[s][t] + h_post[t]*h_pre[s]
                                  // (stored t-major so each output t reads one row)

// --------------------------------------------------------------------------
// Tiny prep: log-domain Sinkhorn on 4x4 + two softmax(4), fused into g_M.
// Single thread; microsecond-scale, irrelevant to total time.
// --------------------------------------------------------------------------
__global__ void prep_kernel(const float* __restrict__ hres_logits,
                            const float* __restrict__ hpre_logits,
                            const float* __restrict__ hpost_logits) {
    float z[NS][NS];
    #pragma unroll
    for (int i = 0; i < NS; i++)
        #pragma unroll
        for (int j = 0; j < NS; j++)
            z[i][j] = hres_logits[i * NS + j] * (1.0f / SINKHORN_TAU);

    float u[NS] = {0.f, 0.f, 0.f, 0.f};
    float v[NS] = {0.f, 0.f, 0.f, 0.f};

    for (int it = 0; it < SINKHORN_ITERS; it++) {
        // u = -logsumexp(z + v[None,:], axis=-1)   (max-subtracted; z ~ +/-60)
        #pragma unroll
        for (int i = 0; i < NS; i++) {
            float m = -1e30f;
            #pragma unroll
            for (int j = 0; j < NS; j++) m = fmaxf(m, z[i][j] + v[j]);
            float s = 0.f;
            #pragma unroll
            for (int j = 0; j < NS; j++) s += __expf(z[i][j] + v[j] - m);
            u[i] = -(m + __logf(s));
        }
        // v = -logsumexp(z + u[:,None], axis=-2)
        #pragma unroll
        for (int j = 0; j < NS; j++) {
            float m = -1e30f;
            #pragma unroll
            for (int i = 0; i < NS; i++) m = fmaxf(m, z[i][j] + u[i]);
            float s = 0.f;
            #pragma unroll
            for (int i = 0; i < NS; i++) s += __expf(z[i][j] + u[i] - m);
            v[j] = -(m + __logf(s));
        }
    }

    float hres[NS][NS];
    #pragma unroll
    for (int i = 0; i < NS; i++)
        #pragma unroll
        for (int j = 0; j < NS; j++)
            hres[i][j] = __expf(z[i][j] + u[i] + v[j]);

    float hpre[NS], hpost[NS];
    {
        float m = -1e30f;
        #pragma unroll
        for (int i = 0; i < NS; i++) m = fmaxf(m, hpre_logits[i]);
        float s = 0.f;
        #pragma unroll
        for (int i = 0; i < NS; i++) { hpre[i] = __expf(hpre_logits[i] - m); s += hpre[i]; }
        float inv = 1.0f / s;
        #pragma unroll
        for (int i = 0; i < NS; i++) hpre[i] *= inv;
    }
    {
        float m = -1e30f;
        #pragma unroll
        for (int i = 0; i < NS; i++) m = fmaxf(m, hpost_logits[i]);
        float s = 0.f;
        #pragma unroll
        for (int i = 0; i < NS; i++) { hpost[i] = __expf(hpost_logits[i] - m); s += hpost[i]; }
        float inv = 1.0f / s;
        #pragma unroll
        for (int i = 0; i < NS; i++) hpost[i] *= inv;
    }

    // t-major: row t holds the 4 coefficients multiplying streams s=0..3
    #pragma unroll
    for (int t = 0; t < NS; t++)
        #pragma unroll
        for (int s = 0; s < NS; s++)
            g_M[t * NS + s] = hres[s][t] + hpost[t] * hpre[s];
}

// --------------------------------------------------------------------------
// Streaming mix: each thread handles one float4 position across all 4
// streams of one batch. 4 independent LDG.128 -> 16 FFMA -> 4 STG.128.
// td4 = float4s per (b,s) plane (runtime-derived).
// --------------------------------------------------------------------------
__global__ __launch_bounds__(256)
void mix_kernel(const float4* __restrict__ x, float4* __restrict__ out,
                int td4) {
    const int idx = blockIdx.x * blockDim.x + threadIdx.x;   // 0 .. td4-1
    if (idx >= td4) return;
    const int b = blockIdx.y;

    // Coefficient rows as 4 x LDG.128 (uniform address, L1-broadcast).
    // mt[t] = (M[t][0], M[t][1], M[t][2], M[t][3])
    const float4* Mv = reinterpret_cast<const float4*>(g_M);
    float4 mt[NS];
    #pragma unroll
    for (int t = 0; t < NS; t++) mt[t] = Mv[t];

    const float4* base = x + (size_t)b * NS * td4 + idx;
    float4 v0 = base[0 * (size_t)td4];     // 4 front-batched independent loads
    float4 v1 = base[1 * (size_t)td4];
    float4 v2 = base[2 * (size_t)td4];
    float4 v3 = base[3 * (size_t)td4];

    float4* obase = out + (size_t)b * NS * td4 + idx;

    #pragma unroll
    for (int t = 0; t < NS; t++) {
        const float c0 = mt[t].x, c1 = mt[t].y, c2 = mt[t].z, c3 = mt[t].w;
        float4 r;
        r.x = c0 * v0.x + c1 * v1.x + c2 * v2.x + c3 * v3.x;
        r.y = c0 * v0.y + c1 * v1.y + c2 * v2.y + c3 * v3.y;
        r.z = c0 * v0.z + c1 * v1.z + c2 * v2.z + c3 * v3.z;
        r.w = c0 * v0.w + c1 * v1.w + c2 * v2.w + c3 * v3.w;
        obase[t * (size_t)td4] = r;
    }
}

extern "C" void kernel_launch(void* const* d_in, const int* in_sizes, int n_in,
                              void* d_out, int out_size) {
    const float* residuals    = (const float*)d_in[0];   // [B*S, T, D]
    const float* hres_logits  = (const float*)d_in[1];   // [S, S]
    const float* hpre_logits  = (const float*)d_in[2];   // [S]
    const float* hpost_logits = (const float*)d_in[3];   // [S]
    float* out = (float*)d_out;

    prep_kernel<<<1, 1>>>(hres_logits, hpre_logits, hpost_logits);

    const int total  = in_sizes[0];          // B*S*T*D  (16*2048*2048)
    const int bs     = 16;                   // leading dim of residuals (B*S)
    const int nb     = bs / NS;              // B = 4
    const int plane  = total / bs;           // T*D per (b,s) plane
    const int td4    = plane / 4;            // float4s per plane
    const int blocks = (td4 + 255) / 256;

    dim3 grid(blocks, nb, 1);
    mix_kernel<<<grid, 256>>>(reinterpret_cast<const float4*>(residuals),
                              reinterpret_cast<float4*>(out), td4);
}

// round 12
// speedup vs baseline: 1.0045x; 1.0045x over previous
#include <cuda_runtime.h>
#include <cuda_bf16.h>

// ===========================================================================
// StaticMHCAdapter: out[b,t] = sum_s (h_res[s,t] + h_post[t]*h_pre[s]) * x[b,s]
// h_res = sinkhorn_log(H_res_logits); h_pre/h_post = softmax.
// x = residuals [B=4, S=4, T, D]. Entire op = 4x4 stream mix -> HBM streaming.
// R12 (= R4 design, unexecuted: broker timeouts R4-R11): VPT=2 (8 front-
// batched LDG.128/thread), __ldcs/__stcs streaming hints, warp-parallel prep,
// unguarded fast path for exact-divisible shapes.
// ===========================================================================

#define NS 4
#define SINKHORN_ITERS 10
#define SINKHORN_TAU 0.05f
#define VPT 2                      // float4s per thread per stream
#define TPB 256

__device__ float g_M[16];          // g_M[t*NS+s], t-major rows

// --------------------------------------------------------------------------
// Warp-parallel prep: rows/cols of the 4x4 Sinkhorn on 4 threads, exchanged
// through shared memory. One warp launched.
// --------------------------------------------------------------------------
__global__ void prep_kernel(const float* __restrict__ hres_logits,
                            const float* __restrict__ hpre_logits,
                            const float* __restrict__ hpost_logits) {
    __shared__ float z[NS][NS];
    __shared__ float u[NS], v[NS];
    __shared__ float hpre[NS], hpost[NS];

    const int t = threadIdx.x;

    if (t < 16) z[t >> 2][t & 3] = hres_logits[t] * (1.0f / SINKHORN_TAU);
    if (t < NS) { u[t] = 0.f; v[t] = 0.f; }
    __syncwarp();

    for (int it = 0; it < SINKHORN_ITERS; it++) {
        // u[i] = -logsumexp_j(z[i][j] + v[j])
        if (t < NS) {
            float a0 = z[t][0] + v[0], a1 = z[t][1] + v[1];
            float a2 = z[t][2] + v[2], a3 = z[t][3] + v[3];
            float m = fmaxf(fmaxf(a0, a1), fmaxf(a2, a3));
            float s = __expf(a0 - m) + __expf(a1 - m) +
                      __expf(a2 - m) + __expf(a3 - m);
            u[t] = -(m + __logf(s));
        }
        __syncwarp();
        // v[j] = -logsumexp_i(z[i][j] + u[i])
        if (t < NS) {
            float a0 = z[0][t] + u[0], a1 = z[1][t] + u[1];
            float a2 = z[2][t] + u[2], a3 = z[3][t] + u[3];
            float m = fmaxf(fmaxf(a0, a1), fmaxf(a2, a3));
            float s = __expf(a0 - m) + __expf(a1 - m) +
                      __expf(a2 - m) + __expf(a3 - m);
            v[t] = -(m + __logf(s));
        }
        __syncwarp();
    }

    if (t < NS) {
        float l0 = hpre_logits[0], l1 = hpre_logits[1],
              l2 = hpre_logits[2], l3 = hpre_logits[3];
        float m = fmaxf(fmaxf(l0, l1), fmaxf(l2, l3));
        float e0 = __expf(l0 - m), e1 = __expf(l1 - m),
              e2 = __expf(l2 - m), e3 = __expf(l3 - m);
        float inv = 1.0f / (e0 + e1 + e2 + e3);
        hpre[t] = ((t == 0) ? e0 : (t == 1) ? e1 : (t == 2) ? e2 : e3) * inv;

        float p0 = hpost_logits[0], p1 = hpost_logits[1],
              p2 = hpost_logits[2], p3 = hpost_logits[3];
        float mp = fmaxf(fmaxf(p0, p1), fmaxf(p2, p3));
        float f0 = __expf(p0 - mp), f1 = __expf(p1 - mp),
              f2 = __expf(p2 - mp), f3 = __expf(p3 - mp);
        float invp = 1.0f / (f0 + f1 + f2 + f3);
        hpost[t] = ((t == 0) ? f0 : (t == 1) ? f1 : (t == 2) ? f2 : f3) * invp;
    }
    __syncwarp();

    // g_M[tcol*NS + s] = exp(z[s][tcol] + u[s] + v[tcol]) + hpost[tcol]*hpre[s]
    if (t < 16) {
        const int tcol = t >> 2, s = t & 3;
        g_M[t] = __expf(z[s][tcol] + u[s] + v[tcol]) + hpost[tcol] * hpre[s];
    }
}

// --------------------------------------------------------------------------
// Mix body shared by both variants. GUARDED=false assumes every idx in range.
// --------------------------------------------------------------------------
template <bool GUARDED>
__device__ __forceinline__
void mix_body(const float4* __restrict__ x, float4* __restrict__ out, int td4) {
    const int base_idx = blockIdx.x * (TPB * VPT) + threadIdx.x;
    const int b = blockIdx.y;
    const size_t plane = (size_t)td4;

    // Coefficient rows first (uniform-address LDG.128, L1-broadcast) —
    // latency hides under the streaming loads below.
    const float4* Mv = reinterpret_cast<const float4*>(g_M);
    float4 mt[NS];
    #pragma unroll
    for (int t = 0; t < NS; t++) mt[t] = Mv[t];

    const float4* bx = x   + (size_t)b * NS * plane;
    float4*       bo = out + (size_t)b * NS * plane;

    // 8 independent, front-batched streaming loads
    float4 v[NS][VPT];
    #pragma unroll
    for (int s = 0; s < NS; s++)
        #pragma unroll
        for (int k = 0; k < VPT; k++) {
            const int idx = base_idx + k * TPB;
            if (!GUARDED || idx < td4) v[s][k] = __ldcs(bx + s * plane + idx);
        }

    #pragma unroll
    for (int t = 0; t < NS; t++) {
        const float c0 = mt[t].x, c1 = mt[t].y, c2 = mt[t].z, c3 = mt[t].w;
        #pragma unroll
        for (int k = 0; k < VPT; k++) {
            const int idx = base_idx + k * TPB;
            if (!GUARDED || idx < td4) {
                float4 r;
                r.x = c0 * v[0][k].x + c1 * v[1][k].x + c2 * v[2][k].x + c3 * v[3][k].x;
                r.y = c0 * v[0][k].y + c1 * v[1][k].y + c2 * v[2][k].y + c3 * v[3][k].y;
                r.z = c0 * v[0][k].z + c1 * v[1][k].z + c2 * v[2][k].z + c3 * v[3][k].z;
                r.w = c0 * v[0][k].w + c1 * v[1][k].w + c2 * v[2][k].w + c3 * v[3][k].w;
                __stcs(bo + t * plane + idx, r);
            }
        }
    }
}

__global__ __launch_bounds__(TPB)
void mix_kernel_exact(const float4* __restrict__ x, float4* __restrict__ out,
                      int td4) {
    mix_body<false>(x, out, td4);
}

__global__ __launch_bounds__(TPB)
void mix_kernel_guarded(const float4* __restrict__ x, float4* __restrict__ out,
                        int td4) {
    mix_body<true>(x, out, td4);
}

extern "C" void kernel_launch(void* const* d_in, const int* in_sizes, int n_in,
                              void* d_out, int out_size) {
    const float* residuals    = (const float*)d_in[0];   // [B*S, T, D]
    const float* hres_logits  = (const float*)d_in[1];   // [S, S]
    const float* hpre_logits  = (const float*)d_in[2];   // [S]
    const float* hpost_logits = (const float*)d_in[3];   // [S]
    float* out = (float*)d_out;

    prep_kernel<<<1, 32>>>(hres_logits, hpre_logits, hpost_logits);

    const int total  = in_sizes[0];          // B*S*T*D
    const int bs     = 16;                   // leading dim (B*S)
    const int nb     = bs / NS;              // B = 4
    const int plane  = total / bs;           // T*D
    const int td4    = plane / 4;            // float4s per plane
    const int chunk  = TPB * VPT;
    const int blocks = (td4 + chunk - 1) / chunk;

    dim3 grid(blocks, nb, 1);
    if (td4 % chunk == 0) {
        mix_kernel_exact<<<grid, TPB>>>(
            reinterpret_cast<const float4*>(residuals),
            reinterpret_cast<float4*>(out), td4);
    } else {
        mix_kernel_guarded<<<grid, TPB>>>(
            reinterpret_cast<const float4*>(residuals),
            reinterpret_cast<float4*>(out), td4);
    }
}